// round 2
// baseline (speedup 1.0000x reference)
#include <cuda_runtime.h>
#include <cuda_bf16.h>

// Scratch: inverse L2 norms per row (N = 100000). Static device array per the
// no-allocation rule. Sized with headroom.
#define MAX_N 131072
__device__ float g_inv[MAX_N];

// Kernel 1: one warp per row computes 1 / max(||row||, 1e-12).
__global__ void norm_kernel(const float* __restrict__ emb, int N) {
    int warps_per_block = blockDim.x >> 5;
    int row = blockIdx.x * warps_per_block + (threadIdx.x >> 5);
    if (row >= N) return;
    int lane = threadIdx.x & 31;
    const float4* r = reinterpret_cast<const float4*>(emb) + (size_t)row * 32;
    float4 v = r[lane];
    float ss = v.x * v.x + v.y * v.y + v.z * v.z + v.w * v.w;
    #pragma unroll
    for (int o = 16; o > 0; o >>= 1)
        ss += __shfl_xor_sync(0xffffffffu, ss, o);
    if (lane == 0)
        g_inv[row] = 1.0f / fmaxf(sqrtf(ss), 1e-12f);
}

// Kernel 2: one warp per edge. Each lane handles 4 consecutive features via
// float4. z[e] = scale * inv[s] * inv[t] * sum_h emb[s][h]*d[h]*emb[t][h].
// NOTE: indices are int32 (JAX x64 disabled -> int64 request degrades to i32).
__global__ void edge_kernel(const float* __restrict__ emb,
                            const int* __restrict__ src,
                            const int* __restrict__ dst,
                            const float* __restrict__ dvec,
                            const float* __restrict__ scale,
                            float* __restrict__ out,
                            int E) {
    int warps_per_block = blockDim.x >> 5;
    int e = blockIdx.x * warps_per_block + (threadIdx.x >> 5);
    if (e >= E) return;
    int lane = threadIdx.x & 31;

    int s = __ldg(&src[e]);
    int t = __ldg(&dst[e]);

    const float4* rs = reinterpret_cast<const float4*>(emb) + (size_t)s * 32;
    const float4* rt = reinterpret_cast<const float4*>(emb) + (size_t)t * 32;
    float4 a = __ldg(&rs[lane]);
    float4 b = __ldg(&rt[lane]);
    float4 dv = __ldg(reinterpret_cast<const float4*>(dvec) + lane);

    float p = a.x * dv.x * b.x
            + a.y * dv.y * b.y
            + a.z * dv.z * b.z
            + a.w * dv.w * b.w;
    #pragma unroll
    for (int o = 16; o > 0; o >>= 1)
        p += __shfl_xor_sync(0xffffffffu, p, o);

    if (lane == 0) {
        float f = g_inv[s] * g_inv[t] * __ldg(scale);
        out[e] = p * f;
    }
}

extern "C" void kernel_launch(void* const* d_in, const int* in_sizes, int n_in,
                              void* d_out, int out_size) {
    const float* emb   = (const float*)d_in[0];
    const int*   src   = (const int*)d_in[1];
    const int*   dst   = (const int*)d_in[2];
    const float* dvec  = (const float*)d_in[3];
    const float* scale = (const float*)d_in[4];
    float* out = (float*)d_out;

    int N = in_sizes[0] / 128;   // H = 128
    int E = in_sizes[1];

    const int TPB = 256;                 // 8 warps per block
    int warps_per_block = TPB / 32;

    int norm_blocks = (N + warps_per_block - 1) / warps_per_block;
    norm_kernel<<<norm_blocks, TPB>>>(emb, N);

    int edge_blocks = (E + warps_per_block - 1) / warps_per_block;
    edge_kernel<<<edge_blocks, TPB>>>(emb, src, dst, dvec, scale, out, E);
}

// round 3
// speedup vs baseline: 1.5586x; 1.5586x over previous
#include <cuda_runtime.h>
#include <cuda_bf16.h>

// Scratch: inverse L2 norms per row (N = 100000). Static device array per the
// no-allocation rule. Sized with headroom.
#define MAX_N 131072
__device__ float g_inv[MAX_N];

// Kernel 1: one warp per row computes 1 / max(||row||, 1e-12).
__global__ void norm_kernel(const float* __restrict__ emb, int N) {
    int warps_per_block = blockDim.x >> 5;
    int row = blockIdx.x * warps_per_block + (threadIdx.x >> 5);
    if (row >= N) return;
    int lane = threadIdx.x & 31;
    const float4* r = reinterpret_cast<const float4*>(emb) + (size_t)row * 32;
    float4 v = r[lane];
    float ss = v.x * v.x + v.y * v.y + v.z * v.z + v.w * v.w;
    #pragma unroll
    for (int o = 16; o > 0; o >>= 1)
        ss += __shfl_xor_sync(0xffffffffu, ss, o);
    if (lane == 0)
        g_inv[row] = 1.0f / fmaxf(sqrtf(ss), 1e-12f);
}

// Kernel 2: 4 edges per warp, 8 lanes per edge. Each lane loads 4 float4 of
// the src row and 4 of the dst row (8 independent LDG.128 in flight -> high
// MLP), FMAs with d, then a 3-deep intra-group shuffle reduce.
// Indices are int32 (JAX x64 disabled).
__global__ void edge_kernel(const float* __restrict__ emb,
                            const int* __restrict__ src,
                            const int* __restrict__ dst,
                            const float* __restrict__ dvec,
                            const float* __restrict__ scale,
                            float* __restrict__ out,
                            int E) {
    int warp = blockIdx.x * (blockDim.x >> 5) + (threadIdx.x >> 5);
    int lane = threadIdx.x & 31;
    int g    = lane >> 3;    // edge group within warp: 0..3
    int l8   = lane & 7;     // lane within group

    int e0 = warp * 4 + g;
    bool valid = (e0 < E);
    int e = valid ? e0 : 0;

    int s = __ldg(&src[e]);
    int t = __ldg(&dst[e]);

    const float4* rs  = reinterpret_cast<const float4*>(emb) + (size_t)s * 32;
    const float4* rt  = reinterpret_cast<const float4*>(emb) + (size_t)t * 32;
    const float4* dv4 = reinterpret_cast<const float4*>(dvec);

    // 8 independent row loads per lane (4 src + 4 dst), plus dvec (L1-hot).
    float4 a0 = __ldg(&rs[l8]);
    float4 a1 = __ldg(&rs[l8 + 8]);
    float4 a2 = __ldg(&rs[l8 + 16]);
    float4 a3 = __ldg(&rs[l8 + 24]);
    float4 b0 = __ldg(&rt[l8]);
    float4 b1 = __ldg(&rt[l8 + 8]);
    float4 b2 = __ldg(&rt[l8 + 16]);
    float4 b3 = __ldg(&rt[l8 + 24]);
    float4 d0 = __ldg(&dv4[l8]);
    float4 d1 = __ldg(&dv4[l8 + 8]);
    float4 d2 = __ldg(&dv4[l8 + 16]);
    float4 d3 = __ldg(&dv4[l8 + 24]);

    float p = 0.0f;
    p += a0.x * d0.x * b0.x; p += a0.y * d0.y * b0.y;
    p += a0.z * d0.z * b0.z; p += a0.w * d0.w * b0.w;
    p += a1.x * d1.x * b1.x; p += a1.y * d1.y * b1.y;
    p += a1.z * d1.z * b1.z; p += a1.w * d1.w * b1.w;
    p += a2.x * d2.x * b2.x; p += a2.y * d2.y * b2.y;
    p += a2.z * d2.z * b2.z; p += a2.w * d2.w * b2.w;
    p += a3.x * d3.x * b3.x; p += a3.y * d3.y * b3.y;
    p += a3.z * d3.z * b3.z; p += a3.w * d3.w * b3.w;

    // Reduce across the 8-lane group (xor offsets stay inside the group).
    p += __shfl_xor_sync(0xffffffffu, p, 4);
    p += __shfl_xor_sync(0xffffffffu, p, 2);
    p += __shfl_xor_sync(0xffffffffu, p, 1);

    if (l8 == 0 && valid) {
        float f = g_inv[s] * g_inv[t] * __ldg(scale);
        out[e] = p * f;   // lanes 0,8,16,24 -> 4 consecutive floats, coalesced
    }
}

extern "C" void kernel_launch(void* const* d_in, const int* in_sizes, int n_in,
                              void* d_out, int out_size) {
    const float* emb   = (const float*)d_in[0];
    const int*   src   = (const int*)d_in[1];
    const int*   dst   = (const int*)d_in[2];
    const float* dvec  = (const float*)d_in[3];
    const float* scale = (const float*)d_in[4];
    float* out = (float*)d_out;

    int N = in_sizes[0] / 128;   // H = 128
    int E = in_sizes[1];

    const int TPB = 256;                 // 8 warps per block
    int warps_per_block = TPB / 32;

    int norm_blocks = (N + warps_per_block - 1) / warps_per_block;
    norm_kernel<<<norm_blocks, TPB>>>(emb, N);

    int edges_per_block = warps_per_block * 4;
    int edge_blocks = (E + edges_per_block - 1) / edges_per_block;
    edge_kernel<<<edge_blocks, TPB>>>(emb, src, dst, dvec, scale, out, E);
}